// round 3
// baseline (speedup 1.0000x reference)
#include <cuda_runtime.h>
#include <math.h>

#define N_NODES 50000
#define E_EDGES 640000
#define HID 128
#define NG 50
#define NGRAPHS 64
#define NBATCH 8          // edges per batch in edge kernel

// ---------------- scratch (static device globals; no allocs allowed) ---------
__device__ __align__(16) float g_ea[(size_t)E_EDGES * NG];   // envelope-folded gaussians
__device__ __align__(16) float g_C[E_EDGES];                 // cosine cutoff
__device__ __align__(16) int   g_src[E_EDGES];
__device__ __align__(16) int   g_dst[E_EDGES];
__device__ __align__(16) float g_h[(size_t)N_NODES * HID];
__device__ __align__(16) float g_xf[(size_t)N_NODES * HID];
__device__ __align__(16) float g_agg[(size_t)N_NODES * HID];
__device__ int g_is64;

typedef unsigned long long u64;

__device__ __forceinline__ u64 pack2(float x, float y) {
    u64 r; asm("mov.b64 %0,{%1,%2};" : "=l"(r) : "f"(x), "f"(y)); return r;
}
__device__ __forceinline__ float2 unpack2(u64 v) {
    float2 f; asm("mov.b64 {%0,%1},%2;" : "=f"(f.x), "=f"(f.y) : "l"(v)); return f;
}
#define FMA2(d, a, b, c) asm("fma.rn.f32x2 %0,%1,%2,%3;" : "=l"(d) : "l"(a), "l"(b), "l"(c))

__device__ __forceinline__ float sspf(float x) {
    // shifted softplus: log(1+e^x) - log(2), numerically stable
    float ax = fabsf(x);
    float sp = log1pf(__expf(-ax));
    return (x > 0.f ? x + sp : sp) - 0.6931471805599453f;
}

// ---------------- dtype sniffer for edge_index -------------------------------
// If edge_index is int64 (little-endian, values < 2^31), odd 32-bit words are 0.
// If int32, odd words are random node ids (nonzero w.p. ~1).
__global__ void detect_kernel(const int* __restrict__ ei) {
    if (threadIdx.x == 0 && blockIdx.x == 0) {
        int acc = ei[1] | ei[3] | ei[5] | ei[7] | ei[9] | ei[11] | ei[13] | ei[15];
        g_is64 = (acc == 0) ? 1 : 0;
    }
}

// ---------------- prep: per-edge geometry + gaussians ------------------------
__global__ void prep_kernel(const int* __restrict__ ei, const float* __restrict__ pos) {
    int e = blockIdx.x * blockDim.x + threadIdx.x;
    if (e >= E_EDGES) return;
    int s, t;
    if (g_is64) {
        const long long* ei64 = (const long long*)ei;
        s = (int)ei64[e];
        t = (int)ei64[E_EDGES + e];
    } else {
        s = ei[e];
        t = ei[E_EDGES + e];
    }
    float dx = pos[t * 3 + 0] - pos[s * 3 + 0];
    float dy = pos[t * 3 + 1] - pos[s * 3 + 1];
    float dz = pos[t * 3 + 2] - pos[s * 3 + 2];
    float d = sqrtf(dx * dx + dy * dy + dz * dz);
    g_src[e] = s;
    g_dst[e] = t;
    g_C[e] = 0.5f * (cosf(d * 0.62831853071795864f) + 1.0f);  // pi/5
    float srel = d * 0.2f;
    float env = 0.f;
    if (srel < 1.f) {
        float dn = 1.f - srel * srel;
        env = expf(1.f - 1.f / dn);
    }
    const float step = 5.0f / 49.0f;
    const float coeff = -0.5f / (step * step);
    #pragma unroll 5
    for (int k = 0; k < NG; k++) {
        float off = step * (float)k;
        float dd = d - off;
        g_ea[(size_t)e * NG + k] = expf(coeff * dd * dd) * env;
    }
}

// ---------------- embedding gather -------------------------------------------
__global__ void embed_kernel(const int* __restrict__ z, const float* __restrict__ emb) {
    int i = blockIdx.x * blockDim.x + threadIdx.x;
    if (i >= N_NODES * HID) return;
    int n = i >> 7, c = i & 127;
    g_h[i] = emb[z[n] * HID + c];
}

// ---------------- node GEMM: [N,128] @ [128,128] with epilogue modes ---------
// MODE 0: C = A@W
// MODE 1: C = ssp(A@W + b)
// MODE 2: C = C + A@W + b   (residual accumulate into Cout)
template <int MODE>
__global__ __launch_bounds__(256) void node_gemm(const float* __restrict__ A,
                                                 const float* __restrict__ W,
                                                 const float* __restrict__ bias,
                                                 float* __restrict__ Cout) {
    extern __shared__ float sm[];
    float* As = sm;               // [128][128] As[r][k]
    float* Ws = sm + 128 * 128;   // [128][128] Ws[k][c]
    int tid = threadIdx.x;
    int row0 = blockIdx.x * 128;
    for (int i = tid; i < 128 * 128; i += 256) {
        int r = i >> 7;
        As[i] = (row0 + r < N_NODES) ? A[(size_t)(row0 + r) * 128 + (i & 127)] : 0.f;
        Ws[i] = W[i];
    }
    __syncthreads();
    int tx = tid & 15, ty = tid >> 4;
    u64 acc[8][4];
    #pragma unroll
    for (int i = 0; i < 8; i++)
        #pragma unroll
        for (int p = 0; p < 4; p++) acc[i][p] = 0ull;

    #pragma unroll 4
    for (int k = 0; k < 128; k++) {
        ulonglong2 b0 = *(const ulonglong2*)&Ws[k * 128 + tx * 8];
        ulonglong2 b1 = *(const ulonglong2*)&Ws[k * 128 + tx * 8 + 4];
        #pragma unroll
        for (int i = 0; i < 8; i++) {
            float a = As[(ty * 8 + i) * 128 + k];
            u64 ad = pack2(a, a);
            FMA2(acc[i][0], ad, b0.x, acc[i][0]);
            FMA2(acc[i][1], ad, b0.y, acc[i][1]);
            FMA2(acc[i][2], ad, b1.x, acc[i][2]);
            FMA2(acc[i][3], ad, b1.y, acc[i][3]);
        }
    }
    int c0 = tx * 8;
    #pragma unroll
    for (int i = 0; i < 8; i++) {
        int row = row0 + ty * 8 + i;
        if (row < N_NODES) {
            float o[8];
            #pragma unroll
            for (int p = 0; p < 4; p++) {
                float2 f = unpack2(acc[i][p]);
                o[2 * p] = f.x;
                o[2 * p + 1] = f.y;
            }
            float* dst = &Cout[(size_t)row * 128 + c0];
            if (MODE == 0) {
                #pragma unroll
                for (int j = 0; j < 8; j++) dst[j] = o[j];
            } else if (MODE == 1) {
                #pragma unroll
                for (int j = 0; j < 8; j++) dst[j] = sspf(o[j] + bias[c0 + j]);
            } else {
                #pragma unroll
                for (int j = 0; j < 8; j++) dst[j] = dst[j] + o[j] + bias[c0 + j];
            }
        }
    }
}

// ---------------- fused edge MLP + modulate + scatter ------------------------
// block = 128 threads (thread j owns output dim j), NBATCH=8 edges per iter.
// f32x2: edges packed in pairs, weights duplicated into both halves.
__global__ __launch_bounds__(128) void edge_kernel(const float* __restrict__ w1,
                                                   const float* __restrict__ b1,
                                                   const float* __restrict__ w2,
                                                   const float* __restrict__ b2) {
    extern __shared__ char smemc[];
    float* w2s  = (float*)smemc;                  // 128*128
    float* eas  = w2s + 128 * 128;                // [50][8]  (k*8 + u), pairs adjacent
    float* tss  = eas + NG * NBATCH;              // [128][8]
    float* msgb = tss + 128 * NBATCH;             // [8][128]
    int*   srcs = (int*)(msgb + NBATCH * 128);    // 8
    int*   dsts = srcs + NBATCH;                  // 8
    float* Cs   = (float*)(dsts + NBATCH);        // 8

    int tid = threadIdx.x;

    // per-thread weight column of w1 in registers
    float w1col[NG];
    #pragma unroll
    for (int k = 0; k < NG; k++) w1col[k] = w1[k * 128 + tid];
    float b1r = b1[tid];
    float b2r = b2[tid];
    for (int i = tid; i < 128 * 128; i += 128) w2s[i] = w2[i];
    __syncthreads();

    const int nb = E_EDGES / NBATCH;
    for (int b = blockIdx.x; b < nb; b += gridDim.x) {
        int base = b * NBATCH;
        if (tid < NBATCH) {
            int e = base + tid;
            srcs[tid] = g_src[e];
            dsts[tid] = g_dst[e];
            Cs[tid] = g_C[e];
        }
        for (int i = tid; i < NG * NBATCH; i += 128) {
            int u = i / NG, k = i - u * NG;
            eas[k * NBATCH + u] = g_ea[(size_t)(base + u) * NG + k];
        }
        __syncthreads();

        // phase 1: t = ea @ w1 + b1  (per output dim tid, 8 edges as 4 f32x2)
        u64 a0 = pack2(b1r, b1r), a1 = a0, a2 = a0, a3 = a0;
        #pragma unroll
        for (int k = 0; k < NG; k++) {
            u64 wd = pack2(w1col[k], w1col[k]);
            ulonglong2 e0 = *(const ulonglong2*)&eas[k * NBATCH];
            ulonglong2 e1 = *(const ulonglong2*)&eas[k * NBATCH + 4];
            FMA2(a0, e0.x, wd, a0);
            FMA2(a1, e0.y, wd, a1);
            FMA2(a2, e1.x, wd, a2);
            FMA2(a3, e1.y, wd, a3);
        }
        {
            float2 f0 = unpack2(a0), f1 = unpack2(a1), f2 = unpack2(a2), f3 = unpack2(a3);
            float* tr = &tss[tid * NBATCH];
            tr[0] = sspf(f0.x); tr[1] = sspf(f0.y);
            tr[2] = sspf(f1.x); tr[3] = sspf(f1.y);
            tr[4] = sspf(f2.x); tr[5] = sspf(f2.y);
            tr[6] = sspf(f3.x); tr[7] = sspf(f3.y);
        }
        __syncthreads();

        // phase 2: W = ssp(t) @ w2 + b2
        a0 = pack2(b2r, b2r); a1 = a0; a2 = a0; a3 = a0;
        #pragma unroll 4
        for (int k = 0; k < 128; k++) {
            float w = w2s[k * 128 + tid];
            u64 wd = pack2(w, w);
            ulonglong2 t0 = *(const ulonglong2*)&tss[k * NBATCH];
            ulonglong2 t1 = *(const ulonglong2*)&tss[k * NBATCH + 4];
            FMA2(a0, t0.x, wd, a0);
            FMA2(a1, t0.y, wd, a1);
            FMA2(a2, t1.x, wd, a2);
            FMA2(a3, t1.y, wd, a3);
        }

        // epilogue: msg = W * C * xf[src]
        {
            float2 f0 = unpack2(a0), f1 = unpack2(a1), f2 = unpack2(a2), f3 = unpack2(a3);
            msgb[0 * 128 + tid] = f0.x * Cs[0] * g_xf[(size_t)srcs[0] * 128 + tid];
            msgb[1 * 128 + tid] = f0.y * Cs[1] * g_xf[(size_t)srcs[1] * 128 + tid];
            msgb[2 * 128 + tid] = f1.x * Cs[2] * g_xf[(size_t)srcs[2] * 128 + tid];
            msgb[3 * 128 + tid] = f1.y * Cs[3] * g_xf[(size_t)srcs[3] * 128 + tid];
            msgb[4 * 128 + tid] = f2.x * Cs[4] * g_xf[(size_t)srcs[4] * 128 + tid];
            msgb[5 * 128 + tid] = f2.y * Cs[5] * g_xf[(size_t)srcs[5] * 128 + tid];
            msgb[6 * 128 + tid] = f3.x * Cs[6] * g_xf[(size_t)srcs[6] * 128 + tid];
            msgb[7 * 128 + tid] = f3.y * Cs[7] * g_xf[(size_t)srcs[7] * 128 + tid];
        }
        __syncthreads();

        // vectorized scatter-add: 8 edges * 128 floats = 256 float4 reductions
        #pragma unroll
        for (int r = 0; r < 2; r++) {
            int q = r * 128 + tid;
            int u = q >> 5;
            int c4 = (q & 31) * 4;
            float4 v = *(const float4*)&msgb[u * 128 + c4];
            float* p = &g_agg[(size_t)dsts[u] * 128 + c4];
            asm volatile("red.global.add.v4.f32 [%0], {%1,%2,%3,%4};"
                         :: "l"(p), "f"(v.x), "f"(v.y), "f"(v.z), "f"(v.w)
                         : "memory");
        }
        __syncthreads();
    }
}

// ---------------- readout: ssp(h@out1+b1)@out2 + b2 -> segment sum -----------
__global__ __launch_bounds__(128) void readout_kernel(const float* __restrict__ w1,
                                                      const float* __restrict__ b1,
                                                      const float* __restrict__ w2,
                                                      const float* __restrict__ b2v,
                                                      const int* __restrict__ batch,
                                                      float* __restrict__ out) {
    __shared__ float w1s[128 * 64];
    __shared__ float w2s2[64];
    __shared__ float hs[2][128];
    __shared__ float red[2][64];
    int tid = threadIdx.x;
    for (int i = tid; i < 128 * 64; i += 128) w1s[i] = w1[i];
    if (tid < 64) w2s2[tid] = w2[tid];
    __syncthreads();

    int half = tid >> 6;     // which of the 2 nodes this thread works on
    int c = tid & 63;        // output column of the hidden layer
    float b1r = b1[c];
    float b2r = b2v[0];

    const int npairs = N_NODES / 2;
    for (int pair = blockIdx.x; pair < npairs; pair += gridDim.x) {
        for (int i = tid; i < 256; i += 128) {
            int nd = pair * 2 + (i >> 7);
            hs[i >> 7][i & 127] = g_h[(size_t)nd * 128 + (i & 127)];
        }
        __syncthreads();
        float acc = b1r;
        #pragma unroll 4
        for (int k = 0; k < 128; k++) acc += hs[half][k] * w1s[k * 64 + c];
        float h2 = sspf(acc);
        red[half][c] = h2 * w2s2[c];
        __syncthreads();
        if (c < 32) {
            float v = red[half][c] + red[half][c + 32];
            #pragma unroll
            for (int off = 16; off >= 1; off >>= 1)
                v += __shfl_down_sync(0xffffffffu, v, off);
            if (c == 0) {
                int node = pair * 2 + half;
                atomicAdd(&out[batch[node]], v + b2r);
            }
        }
        __syncthreads();
    }
}

// ---------------- launch ------------------------------------------------------
extern "C" void kernel_launch(void* const* d_in, const int* in_sizes, int n_in,
                              void* d_out, int out_size) {
    const int*       z       = (const int*)d_in[0];
    const float*     pos     = (const float*)d_in[1];
    const int*       ei      = (const int*)d_in[2];   // int32 or int64 (sniffed on device)
    const int*       batch   = (const int*)d_in[3];
    const float*     emb     = (const float*)d_in[4];
    const float*     mlp_w1  = (const float*)d_in[5];
    const float*     mlp_b1  = (const float*)d_in[6];
    const float*     mlp_w2  = (const float*)d_in[7];
    const float*     mlp_b2  = (const float*)d_in[8];
    const float*     conv1_w = (const float*)d_in[9];
    const float*     conv2_w = (const float*)d_in[10];
    const float*     conv2_b = (const float*)d_in[11];
    const float*     lin_w   = (const float*)d_in[12];
    const float*     lin_b   = (const float*)d_in[13];
    const float*     out1_w  = (const float*)d_in[14];
    const float*     out1_b  = (const float*)d_in[15];
    const float*     out2_w  = (const float*)d_in[16];
    const float*     out2_b  = (const float*)d_in[17];

    const int GEMM_SMEM = 2 * 128 * 128 * 4;  // 131072
    const int EDGE_SMEM = (128 * 128 + NG * NBATCH + 128 * NBATCH + NBATCH * 128) * 4
                          + NBATCH * 4 * 3;   // w2s + eas + tss + msgb + meta

    cudaFuncSetAttribute(node_gemm<0>, cudaFuncAttributeMaxDynamicSharedMemorySize, GEMM_SMEM);
    cudaFuncSetAttribute(node_gemm<1>, cudaFuncAttributeMaxDynamicSharedMemorySize, GEMM_SMEM);
    cudaFuncSetAttribute(node_gemm<2>, cudaFuncAttributeMaxDynamicSharedMemorySize, GEMM_SMEM);
    cudaFuncSetAttribute(edge_kernel, cudaFuncAttributeMaxDynamicSharedMemorySize, EDGE_SMEM);

    float *hP, *xfP, *aggP;
    cudaGetSymbolAddress((void**)&hP, g_h);
    cudaGetSymbolAddress((void**)&xfP, g_xf);
    cudaGetSymbolAddress((void**)&aggP, g_agg);

    detect_kernel<<<1, 32>>>(ei);
    prep_kernel<<<(E_EDGES + 255) / 256, 256>>>(ei, pos);
    embed_kernel<<<(N_NODES * HID + 255) / 256, 256>>>(z, emb);

    const int gemm_grid = (N_NODES + 127) / 128;  // 391
    for (int l = 0; l < 3; l++) {
        node_gemm<0><<<gemm_grid, 256, GEMM_SMEM>>>(hP, conv1_w + (size_t)l * 128 * 128, nullptr, xfP);
        cudaMemsetAsync(aggP, 0, (size_t)N_NODES * 128 * sizeof(float));
        edge_kernel<<<444, 128, EDGE_SMEM>>>(mlp_w1 + (size_t)l * NG * 128,
                                             mlp_b1 + (size_t)l * 128,
                                             mlp_w2 + (size_t)l * 128 * 128,
                                             mlp_b2 + (size_t)l * 128);
        node_gemm<1><<<gemm_grid, 256, GEMM_SMEM>>>(aggP, conv2_w + (size_t)l * 128 * 128,
                                                    conv2_b + (size_t)l * 128, xfP);
        node_gemm<2><<<gemm_grid, 256, GEMM_SMEM>>>(xfP, lin_w + (size_t)l * 128 * 128,
                                                    lin_b + (size_t)l * 128, hP);
    }

    cudaMemsetAsync(d_out, 0, NGRAPHS * sizeof(float));
    readout_kernel<<<1024, 128>>>(out1_w, out1_b, out2_w, out2_b, batch, (float*)d_out);
}